// round 16
// baseline (speedup 1.0000x reference)
#include <cuda_runtime.h>
#include <cuda_fp16.h>
#include <cstdint>
#include <cstddef>

// ============================================================================
// TT linear layer, fused Kronecker-sandwich, register-resident Z, 3 warp
// contexts per SMSP (round-11/15 champion + two latency-overlap reorders):
//   Y_b = sum_{r2=0..15}  L2_r2 (64x64) . X_b (64x64) . R2_r2^T (64x64)
// CTA = 6 samples, 384 threads = 12 warps. Warp w: sample s=w>>1, n34-half w&1.
//   GEMM1 (per r2): z[32 n34][64 m12] = R2_r2 . X_s^T   (X via LDSM per iter)
//   GEMM2 (per r2): per ks: lB LDSM FIRST (independent), then pack zA
//                   (depends on GEMM1 tail MMAs), then 8 MMAs -- LDSM latency
//                   overlaps the z dependency wait instead of following it.
// Prologue: factor prefetches issued BEFORE the X load so cp.async GMEM
// latency hides under X's LDG/STS stream.
// Factor ring: 8 slots {R2(j), L2(j)}, prefetch distance 4, barrier every 4
// (4x4 window nesting, both loops ROLLED -- R13: unrolling blows L0 I$).
// Grid = ceil(8192/6) = 1366 ~= 9 waves on 152 SMs.
// ============================================================================

__device__ __forceinline__ uint32_t smem_u32(const void* p) {
    uint32_t a;
    asm("{ .reg .u64 t; cvta.to.shared.u64 t, %1; cvt.u32.u64 %0, t; }" : "=r"(a) : "l"(p));
    return a;
}
__device__ __forceinline__ void cpa16(uint32_t d, const void* s) {
    asm volatile("cp.async.cg.shared.global [%0], [%1], 16;" :: "r"(d), "l"(s));
}
#define CP_COMMIT() asm volatile("cp.async.commit_group;" ::: "memory")
#define CP_WAIT0()  asm volatile("cp.async.wait_group 0;" ::: "memory")

// D += A*B (accumulate)
#define MMA16(d, a0, a1, a2, a3, b0, b1) asm volatile( \
    "mma.sync.aligned.m16n8k16.row.col.f32.f16.f16.f32 " \
    "{%0,%1,%2,%3},{%4,%5,%6,%7},{%8,%9},{%0,%1,%2,%3};" \
    : "+f"((d)[0]), "+f"((d)[1]), "+f"((d)[2]), "+f"((d)[3]) \
    : "r"(a0), "r"(a1), "r"(a2), "r"(a3), "r"(b0), "r"(b1))

// D = A*B (fresh write, C = 0)
#define MMA16Z(d, a0, a1, a2, a3, b0, b1) asm volatile( \
    "mma.sync.aligned.m16n8k16.row.col.f32.f16.f16.f32 " \
    "{%0,%1,%2,%3},{%4,%5,%6,%7},{%8,%9},{%10,%10,%10,%10};" \
    : "=f"((d)[0]), "=f"((d)[1]), "=f"((d)[2]), "=f"((d)[3]) \
    : "r"(a0), "r"(a1), "r"(a2), "r"(a3), "r"(b0), "r"(b1), "f"(0.f))

#define LDSM4(r0, r1, r2_, r3, addr) asm volatile( \
    "ldmatrix.sync.aligned.m8n8.x4.shared.b16 {%0,%1,%2,%3}, [%4];" \
    : "=r"(r0), "=r"(r1), "=r"(r2_), "=r"(r3) : "r"(addr))

__device__ __forceinline__ uint32_t packh2(float lo, float hi) {
    uint32_t r;
    asm("cvt.rn.f16x2.f32 %0, %2, %1;" : "=r"(r) : "f"(lo), "f"(hi));
    return r;
}

// ---------------- layout constants (fp16 element units) --------------------
static constexpr int THREADS = 384;
static constexpr int NSAMP   = 6;      // samples per CTA
static constexpr int LDX = 72;         // X   [384][64]   (144B rows, LDSM-safe)
static constexpr int LDR = 72;         // R/L [64][64]
static constexpr int OFF_X = 0;                          // 384*72 = 27648
static constexpr int OFF_F = 27648;
static constexpr int FBUF  = 2 * 64 * LDR;               // 9216 halves {R | L}
static constexpr int NSLOT = 8;                          // factor ring depth
static constexpr int SMEM_HALFS = OFF_F + NSLOT * FBUF;  // 101376
static constexpr uint32_t SMEM_BYTES = SMEM_HALFS * 2;   // 202752 (< 227KB)
static constexpr uint32_t LHALF = (uint32_t)(64 * LDR) * 2u;
static constexpr uint32_t FSTRIDE = (uint32_t)FBUF * 2u; // slot stride, bytes

// ---------------- device-side factor slices --------------------------------
__device__ __half g_R2h[16 * 64 * 64];   // [r2][n34][m34]
__device__ __half g_L2h[16 * 64 * 64];   // [r2][n12][m12]

// ---------------- prep: both factor contractions in one kernel -------------
__global__ void k_prep(const float* __restrict__ c0, const float* __restrict__ c1,
                       const float* __restrict__ c2, const float* __restrict__ c3) {
    int t = blockIdx.x * 256 + threadIdx.x;      // 0..131071
    if (t < 65536) {
        int m34 = t & 63, n34 = (t >> 6) & 63, r2 = t >> 12;
        int m3 = m34 >> 3, m4 = m34 & 7, n3 = n34 >> 3, n4 = n34 & 7;
        float s = 0.f;
#pragma unroll
        for (int r3 = 0; r3 < 16; r3++)
            s += c2[((r2 * 8 + n3) * 8 + m3) * 16 + r3] * c3[(r3 * 8 + n4) * 8 + m4];
        g_R2h[t] = __float2half_rn(s);
    } else {
        int u = t - 65536;
        int m12 = u & 63, n12 = (u >> 6) & 63, r2 = u >> 12;
        int m1 = m12 >> 3, m2 = m12 & 7, n1 = n12 >> 3, n2 = n12 & 7;
        float s = 0.f;
#pragma unroll
        for (int r1 = 0; r1 < 16; r1++)
            s += c0[(n1 * 8 + m1) * 16 + r1] * c1[((r1 * 8 + n2) * 8 + m2) * 16 + r2];
        g_L2h[u] = __float2half_rn(s);
    }
}

// ---------------- prefetch slot j&7 = { R2(j), L2(j) } (own commit group) ---
__device__ __forceinline__ void prefetch_slot(uint32_t sb, int tid, int j) {
    const uint32_t f0 = sb + (uint32_t)(OFF_F + (j & (NSLOT - 1)) * FBUF) * 2u;
    const __half* gR = g_R2h + j * 4096;
    const __half* gL = g_L2h + j * 4096;
    for (int i = tid; i < 512; i += THREADS) {   // 512 16B chunks per factor
        int row = i >> 3, c = i & 7;
        uint32_t d = (uint32_t)(row * LDR + c * 8) * 2u;
        cpa16(f0 + d, gR + row * 64 + c * 8);
        cpa16(f0 + LHALF + d, gL + row * 64 + c * 8);
    }
    CP_COMMIT();
}

// ---------------- fused main kernel -----------------------------------------
__global__ void __launch_bounds__(THREADS, 1)
tt_fused(const float* __restrict__ x, const float* __restrict__ bias,
         float* __restrict__ y) {
    extern __shared__ __half sm[];
    const uint32_t sb = smem_u32(sm);
    const int tid = threadIdx.x, wid = tid >> 5, lane = tid & 31;
    const int g = lane >> 2, t4 = lane & 3;
    const int b0 = blockIdx.x * NSAMP;

    const int s      = wid >> 1;      // warp's sample slot (0..5)
    const int half34 = wid & 1;       // warp's n34-half
    const int bs     = b0 + s;        // global sample (tail CTA may overflow)

    const int aRow = lane & 15,                      aCol = (lane >> 4) * 8;
    const int bRow = ((lane >> 4) * 8) + (lane & 7), bCol = ((lane >> 3) & 1) * 8;

    // ---- factor prefetches FIRST: their GMEM latency hides under X load ----
    prefetch_slot(sb, tid, 0);
    prefetch_slot(sb, tid, 1);
    prefetch_slot(sb, tid, 2);
    prefetch_slot(sb, tid, 3);

    // ---- load X (6 samples x 4096 fp32) -> fp16 SMEM [(s,m12)][m34] --------
    // tail CTA: clamp sample (duplicate loads; stores guarded)
    {
        __half* sX = sm + OFF_X;
        const float4* gx = reinterpret_cast<const float4*>(x);
#pragma unroll
        for (int j = 0; j < 16; j++) {
            int i = tid + j * THREADS;       // 0..6143 float4 units
            int row = i >> 4, c = i & 15;    // row 0..383
            int gsamp = b0 + (row >> 6);
            if (gsamp > 8191) gsamp = 8191;
            float4 v = gx[(size_t)gsamp * 1024 + (row & 63) * 16 + c];
            *reinterpret_cast<__half2*>(sX + row * LDX + c * 4)     = __floats2half2_rn(v.x, v.y);
            *reinterpret_cast<__half2*>(sX + row * LDX + c * 4 + 2) = __floats2half2_rn(v.z, v.w);
        }
    }
    CP_WAIT0();
    __syncthreads();           // X + slots 0..3 published

    float accY[2][8][4];
#pragma unroll
    for (int a = 0; a < 2; a++)
#pragma unroll
        for (int b = 0; b < 8; b++)
#pragma unroll
            for (int d = 0; d < 4; d++) accY[a][b][d] = 0.f;

    const uint32_t xbase = sb + (uint32_t)(OFF_X + (s * 64 + bRow) * LDX + bCol) * 2u;
    const uint32_t fBase = sb + (uint32_t)OFF_F * 2u;
    const uint32_t fEnd  = fBase + (uint32_t)NSLOT * FSTRIDE;
    uint32_t slotB = fBase;    // current ring slot base, advanced + wrapped

#pragma unroll 1
    for (int w = 0; w < 4; w++) {
#pragma unroll 1
        for (int ii = 0; ii < 4; ii++) {
            const int i = w * 4 + ii;
            // prefetch distance 4, one slot per iteration (R11 schedule)
            if (i + 4 < 16) prefetch_slot(sb, tid, i + 4);

            const uint32_t fR = slotB;
            const uint32_t fL = slotB + LHALF;

            // ---- GEMM1: z[32 n34][64 m12] = R2_r2 . X^T (fresh @ ks=0) -----
            float z[2][8][4];
#pragma unroll
            for (int ks = 0; ks < 4; ks++) {
                uint32_t af[2][4];
#pragma unroll
                for (int mt = 0; mt < 2; mt++) {
                    uint32_t addr = fR + (uint32_t)((half34 * 32 + mt * 16 + aRow) * LDR
                                                    + ks * 16 + aCol) * 2u;
                    LDSM4(af[mt][0], af[mt][1], af[mt][2], af[mt][3], addr);
                }
#pragma unroll
                for (int p = 0; p < 4; p++) {
                    uint32_t xb0, xb1, xb2, xb3;
                    LDSM4(xb0, xb1, xb2, xb3,
                          xbase + (uint32_t)(p * 16 * LDX + ks * 16) * 2u);
#pragma unroll
                    for (int mt = 0; mt < 2; mt++) {
                        if (ks == 0) {
                            MMA16Z(z[mt][2 * p],     af[mt][0], af[mt][1], af[mt][2], af[mt][3],
                                   xb0, xb1);
                            MMA16Z(z[mt][2 * p + 1], af[mt][0], af[mt][1], af[mt][2], af[mt][3],
                                   xb2, xb3);
                        } else {
                            MMA16(z[mt][2 * p],     af[mt][0], af[mt][1], af[mt][2], af[mt][3],
                                  xb0, xb1);
                            MMA16(z[mt][2 * p + 1], af[mt][0], af[mt][1], af[mt][2], af[mt][3],
                                  xb2, xb3);
                        }
                    }
                }
            }

            // ---- GEMM2: per ks -- lB LDSM first (independent), then pack ---
#pragma unroll
            for (int ks = 0; ks < 4; ks++) {
                uint32_t lB[4][4];
#pragma unroll
                for (int q = 0; q < 4; q++) {
                    uint32_t addr = fL + (uint32_t)((q * 16 + bRow) * LDR
                                                    + ks * 16 + bCol) * 2u;
                    LDSM4(lB[q][0], lB[q][1], lB[q][2], lB[q][3], addr);
                }
                uint32_t zA[2][4];
#pragma unroll
                for (int mt = 0; mt < 2; mt++) {
                    zA[mt][0] = packh2(z[mt][2 * ks][0],     z[mt][2 * ks][1]);
                    zA[mt][1] = packh2(z[mt][2 * ks][2],     z[mt][2 * ks][3]);
                    zA[mt][2] = packh2(z[mt][2 * ks + 1][0], z[mt][2 * ks + 1][1]);
                    zA[mt][3] = packh2(z[mt][2 * ks + 1][2], z[mt][2 * ks + 1][3]);
                }
#pragma unroll
                for (int q = 0; q < 4; q++)
#pragma unroll
                    for (int mt = 0; mt < 2; mt++) {
                        MMA16(accY[mt][2 * q],     zA[mt][0], zA[mt][1], zA[mt][2], zA[mt][3],
                              lB[q][0], lB[q][1]);
                        MMA16(accY[mt][2 * q + 1], zA[mt][0], zA[mt][1], zA[mt][2], zA[mt][3],
                              lB[q][2], lB[q][3]);
                    }
            }

            // advance ring slot base with predicated wrap (no per-iter modulo)
            slotB += FSTRIDE;
            if (slotB == fEnd) slotB = fBase;
        }

        // window boundary: publish slots prefetched during this window
        if (w < 3) {
            CP_WAIT0();
            __syncthreads();
        }
    }

    // ---- epilogue: y[bs][n12*64 + n34] = accY + bias (guard tail) ----------
    if (bs < 8192) {
        float* yb = y + (size_t)bs * 4096;
#pragma unroll
        for (int mt = 0; mt < 2; mt++) {
            const int n34r = half34 * 32 + mt * 16 + g;
#pragma unroll
            for (int n8 = 0; n8 < 8; n8++) {
                const int n12c = n8 * 8 + t4 * 2;
                const int e00 = n12c * 64 + n34r;
                const int e10 = e00 + 64;
                yb[e00]     = accY[mt][n8][0] + __ldg(bias + e00);
                yb[e10]     = accY[mt][n8][1] + __ldg(bias + e10);
                yb[e00 + 8] = accY[mt][n8][2] + __ldg(bias + e00 + 8);
                yb[e10 + 8] = accY[mt][n8][3] + __ldg(bias + e10 + 8);
            }
        }
    }
}

// ---------------- launch -----------------------------------------------------
extern "C" void kernel_launch(void* const* d_in, const int* in_sizes, int n_in,
                              void* d_out, int out_size) {
    const float* x    = (const float*)d_in[0];
    const float* c0   = (const float*)d_in[1];
    const float* c1   = (const float*)d_in[2];
    const float* c2   = (const float*)d_in[3];
    const float* c3   = (const float*)d_in[4];
    const float* bias = (const float*)d_in[5];
    float* out = (float*)d_out;

    k_prep<<<512, 256>>>(c0, c1, c2, c3);

    cudaFuncSetAttribute(tt_fused, cudaFuncAttributeMaxDynamicSharedMemorySize, SMEM_BYTES);
    const int grid = (8192 + NSAMP - 1) / NSAMP;   // 1366 ~= 9 waves on 152 SMs
    tt_fused<<<grid, THREADS, SMEM_BYTES>>>(x, bias, out);
}

// round 17
// speedup vs baseline: 1.0067x; 1.0067x over previous
#include <cuda_runtime.h>
#include <cuda_fp16.h>
#include <cstdint>
#include <cstddef>

// ============================================================================
// TT linear layer, fused Kronecker-sandwich, register-resident Z, 3 warp
// contexts per SMSP — the round-11 champion, banked verbatim.
//   Y_b = sum_{r2=0..15}  L2_r2 (64x64) . X_b (64x64) . R2_r2^T (64x64)
// CTA = 6 samples, 384 threads = 12 warps. Warp w: sample s=w>>1, n34-half w&1.
//   GEMM1 (per r2): z[32 n34][64 m12] = R2_r2 . X_s^T   (X via LDSM per iter;
//       X B-frag reload keeps the footprint <=170 regs so 3 warps fit per
//       SMSP: 32*170*3 = 16320 <= 16384)
//   GEMM2 (per r2): accY[32 n34][64 n12] += pack(z) . L2^T (pack folded / ks;
//       GEMM1's fp32 accumulator is repacked in registers as GEMM2's A operand
//       -- no SMEM intermediate ever touches memory)
// Factor ring: 8 slots {R2(j), L2(j)}, prefetch distance 4 (one slot per iter,
// own commit group), barrier every 4 iters. r2 loop ROLLED (unrolling blows
// L0 I$ -- measured). Grid = ceil(8192/6) = 1366 ~= 9 waves on 152 SMs.
// Session: 1436.8 -> 320.9 us (4.48x), rel_err 4.15e-4 stable.
// ============================================================================

__device__ __forceinline__ uint32_t smem_u32(const void* p) {
    uint32_t a;
    asm("{ .reg .u64 t; cvta.to.shared.u64 t, %1; cvt.u32.u64 %0, t; }" : "=r"(a) : "l"(p));
    return a;
}
__device__ __forceinline__ void cpa16(uint32_t d, const void* s) {
    asm volatile("cp.async.cg.shared.global [%0], [%1], 16;" :: "r"(d), "l"(s));
}
#define CP_COMMIT() asm volatile("cp.async.commit_group;" ::: "memory")
#define CP_WAIT0()  asm volatile("cp.async.wait_group 0;" ::: "memory")

// D += A*B (accumulate)
#define MMA16(d, a0, a1, a2, a3, b0, b1) asm volatile( \
    "mma.sync.aligned.m16n8k16.row.col.f32.f16.f16.f32 " \
    "{%0,%1,%2,%3},{%4,%5,%6,%7},{%8,%9},{%0,%1,%2,%3};" \
    : "+f"((d)[0]), "+f"((d)[1]), "+f"((d)[2]), "+f"((d)[3]) \
    : "r"(a0), "r"(a1), "r"(a2), "r"(a3), "r"(b0), "r"(b1))

// D = A*B (fresh write, C = 0)
#define MMA16Z(d, a0, a1, a2, a3, b0, b1) asm volatile( \
    "mma.sync.aligned.m16n8k16.row.col.f32.f16.f16.f32 " \
    "{%0,%1,%2,%3},{%4,%5,%6,%7},{%8,%9},{%10,%10,%10,%10};" \
    : "=f"((d)[0]), "=f"((d)[1]), "=f"((d)[2]), "=f"((d)[3]) \
    : "r"(a0), "r"(a1), "r"(a2), "r"(a3), "r"(b0), "r"(b1), "f"(0.f))

#define LDSM4(r0, r1, r2_, r3, addr) asm volatile( \
    "ldmatrix.sync.aligned.m8n8.x4.shared.b16 {%0,%1,%2,%3}, [%4];" \
    : "=r"(r0), "=r"(r1), "=r"(r2_), "=r"(r3) : "r"(addr))

__device__ __forceinline__ uint32_t packh2(float lo, float hi) {
    uint32_t r;
    asm("cvt.rn.f16x2.f32 %0, %2, %1;" : "=r"(r) : "f"(lo), "f"(hi));
    return r;
}

// ---------------- layout constants (fp16 element units) --------------------
static constexpr int THREADS = 384;
static constexpr int NSAMP   = 6;      // samples per CTA
static constexpr int LDX = 72;         // X   [384][64]   (144B rows, LDSM-safe)
static constexpr int LDR = 72;         // R/L [64][64]
static constexpr int OFF_X = 0;                          // 384*72 = 27648
static constexpr int OFF_F = 27648;
static constexpr int FBUF  = 2 * 64 * LDR;               // 9216 halves {R | L}
static constexpr int NSLOT = 8;                          // factor ring depth
static constexpr int SMEM_HALFS = OFF_F + NSLOT * FBUF;  // 101376
static constexpr uint32_t SMEM_BYTES = SMEM_HALFS * 2;   // 202752 (< 227KB)
static constexpr uint32_t LHALF = (uint32_t)(64 * LDR) * 2u;

// ---------------- device-side factor slices --------------------------------
__device__ __half g_R2h[16 * 64 * 64];   // [r2][n34][m34]
__device__ __half g_L2h[16 * 64 * 64];   // [r2][n12][m12]

// ---------------- prep: both factor contractions in one kernel -------------
__global__ void k_prep(const float* __restrict__ c0, const float* __restrict__ c1,
                       const float* __restrict__ c2, const float* __restrict__ c3) {
    int t = blockIdx.x * 256 + threadIdx.x;      // 0..131071
    if (t < 65536) {
        int m34 = t & 63, n34 = (t >> 6) & 63, r2 = t >> 12;
        int m3 = m34 >> 3, m4 = m34 & 7, n3 = n34 >> 3, n4 = n34 & 7;
        float s = 0.f;
#pragma unroll
        for (int r3 = 0; r3 < 16; r3++)
            s += c2[((r2 * 8 + n3) * 8 + m3) * 16 + r3] * c3[(r3 * 8 + n4) * 8 + m4];
        g_R2h[t] = __float2half_rn(s);
    } else {
        int u = t - 65536;
        int m12 = u & 63, n12 = (u >> 6) & 63, r2 = u >> 12;
        int m1 = m12 >> 3, m2 = m12 & 7, n1 = n12 >> 3, n2 = n12 & 7;
        float s = 0.f;
#pragma unroll
        for (int r1 = 0; r1 < 16; r1++)
            s += c0[(n1 * 8 + m1) * 16 + r1] * c1[((r1 * 8 + n2) * 8 + m2) * 16 + r2];
        g_L2h[u] = __float2half_rn(s);
    }
}

// ---------------- prefetch slot j&7 = { R2(j), L2(j) } ----------------------
__device__ __forceinline__ void prefetch_slot(uint32_t sb, int tid, int j) {
    const uint32_t f0 = sb + (uint32_t)(OFF_F + (j & (NSLOT - 1)) * FBUF) * 2u;
    const __half* gR = g_R2h + j * 4096;
    const __half* gL = g_L2h + j * 4096;
    for (int i = tid; i < 512; i += THREADS) {   // 512 16B chunks per factor
        int row = i >> 3, c = i & 7;
        uint32_t d = (uint32_t)(row * LDR + c * 8) * 2u;
        cpa16(f0 + d, gR + row * 64 + c * 8);
        cpa16(f0 + LHALF + d, gL + row * 64 + c * 8);
    }
    CP_COMMIT();
}

// ---------------- fused main kernel -----------------------------------------
__global__ void __launch_bounds__(THREADS, 1)
tt_fused(const float* __restrict__ x, const float* __restrict__ bias,
         float* __restrict__ y) {
    extern __shared__ __half sm[];
    const uint32_t sb = smem_u32(sm);
    const int tid = threadIdx.x, wid = tid >> 5, lane = tid & 31;
    const int g = lane >> 2, t4 = lane & 3;
    const int b0 = blockIdx.x * NSAMP;

    const int s      = wid >> 1;      // warp's sample slot (0..5)
    const int half34 = wid & 1;       // warp's n34-half
    const int bs     = b0 + s;        // global sample (tail CTA may overflow)

    const int aRow = lane & 15,                      aCol = (lane >> 4) * 8;
    const int bRow = ((lane >> 4) * 8) + (lane & 7), bCol = ((lane >> 3) & 1) * 8;

    // ---- load X (6 samples x 4096 fp32) -> fp16 SMEM [(s,m12)][m34] --------
    // tail CTA: clamp sample (duplicate loads; stores guarded)
    {
        __half* sX = sm + OFF_X;
        const float4* gx = reinterpret_cast<const float4*>(x);
#pragma unroll
        for (int j = 0; j < 16; j++) {
            int i = tid + j * THREADS;       // 0..6143 float4 units
            int row = i >> 4, c = i & 15;    // row 0..383
            int gsamp = b0 + (row >> 6);
            if (gsamp > 8191) gsamp = 8191;
            float4 v = gx[(size_t)gsamp * 1024 + (row & 63) * 16 + c];
            *reinterpret_cast<__half2*>(sX + row * LDX + c * 4)     = __floats2half2_rn(v.x, v.y);
            *reinterpret_cast<__half2*>(sX + row * LDX + c * 4 + 2) = __floats2half2_rn(v.z, v.w);
        }
    }
    prefetch_slot(sb, tid, 0);
    prefetch_slot(sb, tid, 1);
    prefetch_slot(sb, tid, 2);
    prefetch_slot(sb, tid, 3);
    CP_WAIT0();
    __syncthreads();           // X + slots 0..3 published

    float accY[2][8][4];
#pragma unroll
    for (int a = 0; a < 2; a++)
#pragma unroll
        for (int b = 0; b < 8; b++)
#pragma unroll
            for (int d = 0; d < 4; d++) accY[a][b][d] = 0.f;

    const uint32_t xbase = sb + (uint32_t)(OFF_X + (s * 64 + bRow) * LDX + bCol) * 2u;

#pragma unroll 1
    for (int i = 0; i < 16; i++) {
        // window boundary: publish slots prefetched during previous window
        if (i && (i & 3) == 0) {
            CP_WAIT0();
            __syncthreads();
        }
        if (i + 4 < 16) prefetch_slot(sb, tid, i + 4);

        const uint32_t fR = sb + (uint32_t)(OFF_F + (i & (NSLOT - 1)) * FBUF) * 2u;
        const uint32_t fL = fR + LHALF;

        // ---- GEMM1: z[32 n34][64 m12] = R2_r2 . X^T  (fresh write at ks=0) --
        float z[2][8][4];
#pragma unroll
        for (int ks = 0; ks < 4; ks++) {
            uint32_t af[2][4];
#pragma unroll
            for (int mt = 0; mt < 2; mt++) {
                uint32_t addr = fR + (uint32_t)((half34 * 32 + mt * 16 + aRow) * LDR
                                                + ks * 16 + aCol) * 2u;
                LDSM4(af[mt][0], af[mt][1], af[mt][2], af[mt][3], addr);
            }
#pragma unroll
            for (int p = 0; p < 4; p++) {
                uint32_t xb0, xb1, xb2, xb3;
                LDSM4(xb0, xb1, xb2, xb3,
                      xbase + (uint32_t)(p * 16 * LDX + ks * 16) * 2u);
#pragma unroll
                for (int mt = 0; mt < 2; mt++) {
                    if (ks == 0) {
                        MMA16Z(z[mt][2 * p],     af[mt][0], af[mt][1], af[mt][2], af[mt][3],
                               xb0, xb1);
                        MMA16Z(z[mt][2 * p + 1], af[mt][0], af[mt][1], af[mt][2], af[mt][3],
                               xb2, xb3);
                    } else {
                        MMA16(z[mt][2 * p],     af[mt][0], af[mt][1], af[mt][2], af[mt][3],
                              xb0, xb1);
                        MMA16(z[mt][2 * p + 1], af[mt][0], af[mt][1], af[mt][2], af[mt][3],
                              xb2, xb3);
                    }
                }
            }
        }

        // ---- GEMM2: accY += pack(z) . L2^T, pack folded per k-group --------
#pragma unroll
        for (int ks = 0; ks < 4; ks++) {
            uint32_t zA[2][4];
#pragma unroll
            for (int mt = 0; mt < 2; mt++) {
                zA[mt][0] = packh2(z[mt][2 * ks][0],     z[mt][2 * ks][1]);
                zA[mt][1] = packh2(z[mt][2 * ks][2],     z[mt][2 * ks][3]);
                zA[mt][2] = packh2(z[mt][2 * ks + 1][0], z[mt][2 * ks + 1][1]);
                zA[mt][3] = packh2(z[mt][2 * ks + 1][2], z[mt][2 * ks + 1][3]);
            }
            uint32_t lB[4][4];
#pragma unroll
            for (int q = 0; q < 4; q++) {
                uint32_t addr = fL + (uint32_t)((q * 16 + bRow) * LDR
                                                + ks * 16 + bCol) * 2u;
                LDSM4(lB[q][0], lB[q][1], lB[q][2], lB[q][3], addr);
            }
#pragma unroll
            for (int q = 0; q < 4; q++)
#pragma unroll
                for (int mt = 0; mt < 2; mt++) {
                    MMA16(accY[mt][2 * q],     zA[mt][0], zA[mt][1], zA[mt][2], zA[mt][3],
                          lB[q][0], lB[q][1]);
                    MMA16(accY[mt][2 * q + 1], zA[mt][0], zA[mt][1], zA[mt][2], zA[mt][3],
                          lB[q][2], lB[q][3]);
                }
        }
    }

    // ---- epilogue: y[bs][n12*64 + n34] = accY + bias (guard tail) ----------
    if (bs < 8192) {
        float* yb = y + (size_t)bs * 4096;
#pragma unroll
        for (int mt = 0; mt < 2; mt++) {
            const int n34r = half34 * 32 + mt * 16 + g;
#pragma unroll
            for (int n8 = 0; n8 < 8; n8++) {
                const int n12c = n8 * 8 + t4 * 2;
                const int e00 = n12c * 64 + n34r;
                const int e10 = e00 + 64;
                yb[e00]     = accY[mt][n8][0] + __ldg(bias + e00);
                yb[e10]     = accY[mt][n8][1] + __ldg(bias + e10);
                yb[e00 + 8] = accY[mt][n8][2] + __ldg(bias + e00 + 8);
                yb[e10 + 8] = accY[mt][n8][3] + __ldg(bias + e10 + 8);
            }
        }
    }
}

// ---------------- launch -----------------------------------------------------
extern "C" void kernel_launch(void* const* d_in, const int* in_sizes, int n_in,
                              void* d_out, int out_size) {
    const float* x    = (const float*)d_in[0];
    const float* c0   = (const float*)d_in[1];
    const float* c1   = (const float*)d_in[2];
    const float* c2   = (const float*)d_in[3];
    const float* c3   = (const float*)d_in[4];
    const float* bias = (const float*)d_in[5];
    float* out = (float*)d_out;

    k_prep<<<512, 256>>>(c0, c1, c2, c3);

    cudaFuncSetAttribute(tt_fused, cudaFuncAttributeMaxDynamicSharedMemorySize, SMEM_BYTES);
    const int grid = (8192 + NSAMP - 1) / NSAMP;   // 1366 ~= 9 waves on 152 SMs
    tt_fused<<<grid, THREADS, SMEM_BYTES>>>(x, bias, out);
}